// round 16
// baseline (speedup 1.0000x reference)
#include <cuda_runtime.h>
#include <math.h>

#define NMAX 4096
#define FMAX 1024
#define IMGF 256.0f
#define SIGMA 3e-05f
#define INV_SIGMA (1.0f / SIGMA)
#define D_HI (17.4f * SIGMA)     // d above this: sigmoid(d/sigma) == 1.0f -> covered
#define D_LO (-30.0f * SIGMA)    // d below this: contribution < 1e-13 -> skip
#define D_CUL_HI (18.0f * SIGMA) // conservative tile/warp full-cover threshold
#define D_CUL_LO (-31.0f * SIGMA)// conservative tile/warp skip threshold

#define NBLK 256            // 16x16 tiles of 16x16 pixels
#define TPB  1024           // 4 threads (lane-grouped) per pixel

// Scratch (no allocations allowed in kernel_launch)
__device__ float  g_partial[NBLK];
__device__ unsigned g_ticket = 0;   // static-init 0; last block resets after use

// ---------------- single fused kernel ----------------
// 256 blocks = 16x16 tiles. 1024 threads: lanes 4p..4p+3 share pixel p.
// Phase 0 (per-block, redundant): thread tid projects face tid's 3 vertices and
//   builds its edge coefficients in registers (identical fp sequence in every
//   block -> bit-identical values; no global round-trip, no prep kernel).
// Phase 1 (block): classify face-vs-tile AABB on those registers; ballot+scan
//   compaction of survivors into smem (ascending face order -> deterministic).
// Phase 2 (warp): 8x1-pixel footprint cull per 32-face chunk; survivors via
//   __fns, quad-sliced across the 4 lanes of each pixel.
// Phase 3: block + grid reduction (ticket; fixed order -> deterministic).
__global__ void __launch_bounds__(TPB, 2) fused_kernel(const float* __restrict__ verts,
                                                       const float* __restrict__ K,
                                                       const float* __restrict__ R,
                                                       const float* __restrict__ t,
                                                       const int* __restrict__ faces,
                                                       const float* __restrict__ image_ref,
                                                       int F, float* __restrict__ out) {
    __shared__ float4   c0[FMAX];
    __shared__ float4   c1[FMAX];
    __shared__ float    c2s[FMAX];
    __shared__ unsigned gmask[32];      // one 32-face group per warp
    __shared__ int      goff[32];
    __shared__ float    wsum[32];
    __shared__ int      s_cnt;
    __shared__ int      s_allcov;
    __shared__ int      s_last;

    int tid   = threadIdx.x;
    int lane  = tid & 31;
    int wid   = tid >> 5;
    int p     = tid >> 2;               // pixel index within tile (0..255)
    int slice = tid & 3;                // face-list slice (0..3)
    int tx = blockIdx.x & 15;
    int ty = blockIdx.x >> 4;
    int col = tx * 16 + (p & 15);
    int row = ty * 16 + (p >> 4);
    int pix = row * 256 + col;

    float px =  (2.0f * (float)col + 1.0f - IMGF) * (1.0f / IMGF);
    float py = -((2.0f * (float)row + 1.0f - IMGF) * (1.0f / IMGF));

    // tile center + half extent (pixel centers span +/- 15/256 around center)
    float cx =  (2.0f * (float)(tx * 16) + 16.0f - IMGF) * (1.0f / IMGF);
    float cy = -((2.0f * (float)(ty * 16) + 16.0f - IMGF) * (1.0f / IMGF));
    const float h = 15.0f / 256.0f;

    // warp footprint: 8 consecutive cols in one row; y exact across the warp.
    int   colbase = tx * 16 + (wid & 1) * 8;
    float wxc = (2.0f * ((float)colbase + 3.5f) + 1.0f - IMGF) * (1.0f / IMGF);
    const float hx = 7.0f / 256.0f;

    if (tid == 0) s_allcov = 0;

    // ---- phase 0: in-register face prep (face tid), all blocks redundantly ----
    float4 f0r = make_float4(0.f, 0.f, 0.f, 0.f);
    float4 f1r = make_float4(0.f, 0.f, 0.f, 0.f);
    float  f2r = 0.f;
    bool   fvalid = (tid < F);
    if (fvalid) {
        // camera params: uniform addresses -> L1 broadcast loads
        float R0 = R[0], R1 = R[1], R2 = R[2];
        float R3 = R[3], R4 = R[4], R5 = R[5];
        float R6 = R[6], R7 = R[7], R8 = R[8];
        float t0 = t[0], t1 = t[1], t2 = t[2];
        float K0 = K[0], K1 = K[1], K2 = K[2];
        float K3 = K[3], K4 = K[4], K5 = K[5];

        int i0 = faces[3 * tid + 0];
        int i1 = faces[3 * tid + 1];
        int i2 = faces[3 * tid + 2];

        float xs[3], ys[3];
        int idx3[3] = {i0, i1, i2};
        #pragma unroll
        for (int k = 0; k < 3; ++k) {
            int i = idx3[k];
            float vx = verts[3 * i + 0];
            float vy = verts[3 * i + 1];
            float vz = verts[3 * i + 2];
            float p0 = R0 * vx + R1 * vy + R2 * vz + t0;
            float p1 = R3 * vx + R4 * vy + R5 * vz + t1;
            float p2 = R6 * vx + R7 * vy + R8 * vz + t2;
            float zd = p2 + 1e-5f;
            float xn = p0 / zd;
            float yn = p1 / zd;
            float u  = K0 * xn + K1 * yn + K2;
            float vv = K3 * xn + K4 * yn + K5;
            vv = IMGF - vv;
            xs[k] = 2.0f * (u  - IMGF * 0.5f) / IMGF;
            ys[k] = 2.0f * (vv - IMGF * 0.5f) / IMGF;
        }
        float x0 = xs[0], y0 = ys[0];
        float x1 = xs[1], y1 = ys[1];
        float x2 = xs[2], y2 = ys[2];

        float area = (x1 - x0) * (y2 - y0) - (y1 - y0) * (x2 - x0);
        float s = (area > 0.0f) ? 1.0f : ((area < 0.0f) ? -1.0f : 0.0f);

        float dx01 = x1 - x0, dy01 = y1 - y0;
        float dx12 = x2 - x1, dy12 = y2 - y1;
        float dx20 = x0 - x2, dy20 = y0 - y2;
        f0r = make_float4(-s * dy01,  s * dx01,  s * (dy01 * x0 - dx01 * y0), -s * dy12);
        f1r = make_float4( s * dx12,  s * (dy12 * x1 - dx12 * y1), -s * dy20,  s * dx20);
        f2r =  s * (dy20 * x2 - dx20 * y2);
    }

    // ---- phase 1: tile classify on registers (one ballot per warp) ----
    {
        bool interesting = false;
        if (fvalid) {
            float w0 = fmaf(f0r.x, cx, fmaf(f0r.y, cy, f0r.z));
            float r0 = (fabsf(f0r.x) + fabsf(f0r.y)) * h;
            float w1 = fmaf(f0r.w, cx, fmaf(f1r.x, cy, f1r.y));
            float r1 = (fabsf(f0r.w) + fabsf(f1r.x)) * h;
            float w2 = fmaf(f1r.z, cx, fmaf(f1r.w, cy, f2r));
            float r2 = (fabsf(f1r.z) + fabsf(f1r.w)) * h;
            float dmin = fminf(w0 - r0, fminf(w1 - r1, w2 - r2));
            float dmax = fminf(w0 + r0, fminf(w1 + r1, w2 + r2));
            if (dmin > D_CUL_HI) {
                s_allcov = 1;           // face fully covers the tile
            } else if (dmax > D_CUL_LO) {
                interesting = true;     // within soft band or partially covering
            }
        }
        unsigned m = __ballot_sync(0xffffffffu, interesting);
        if (lane == 0) gmask[wid] = m;
    }
    __syncthreads();

    float cov;
    if (s_allcov) {
        cov = 1.0f;                     // whole tile covered: no per-pixel loop
    } else {
        // ---- deterministic exclusive scan of 32 group popcounts (warp 0) ----
        if (tid < 32) {
            int cnt = __popc(gmask[tid]);
            int x = cnt;
            #pragma unroll
            for (int off = 1; off < 32; off <<= 1) {
                int y = __shfl_up_sync(0xffffffffu, x, off);
                if (tid >= off) x += y;
            }
            goff[tid] = x - cnt;
            if (tid == 31) s_cnt = x;
        }
        __syncthreads();

        // ---- coefficient compaction (fixed order: ascending face index) ----
        {
            unsigned m = gmask[wid];
            if (m & (1u << lane)) {
                int pos = goff[wid] + __popc(m & ((1u << lane) - 1u));
                c0[pos]  = f0r;
                c1[pos]  = f1r;
                c2s[pos] = f2r;
            }
        }
        __syncthreads();
        int cnt = s_cnt;

        // ---- phase 2: warp-footprint culled loop over compacted faces ----
        float acc = 0.0f;
        bool covered = false;
        int nchunk = (cnt + 31) >> 5;
        for (int ch = 0; ch < nchunk; ++ch) {
            int base = ch << 5;
            int f = base + lane;
            bool fullcov = false;
            bool interesting = false;
            if (f < cnt) {
                float4 a  = c0[f];
                float4 b  = c1[f];
                float  cc = c2s[f];
                // y exact (warp is one row): w_e at (wxc, py); radius only in x.
                float w0 = fmaf(a.x, wxc, fmaf(a.y, py, a.z));
                float r0 = fabsf(a.x) * hx;
                float w1 = fmaf(a.w, wxc, fmaf(b.x, py, b.y));
                float r1 = fabsf(a.w) * hx;
                float w2 = fmaf(b.z, wxc, fmaf(b.w, py, cc));
                float r2 = fabsf(b.z) * hx;
                float dmin = fminf(w0 - r0, fminf(w1 - r1, w2 - r2));
                float dmax = fminf(w0 + r0, fminf(w1 + r1, w2 + r2));
                fullcov = (dmin > D_CUL_HI);
                interesting = (!fullcov) && (dmax > D_CUL_LO);
            }
            unsigned covm = __ballot_sync(0xffffffffu, fullcov);
            if (covm) { covered = true; break; }   // whole 8-px footprint covered
            unsigned m = __ballot_sync(0xffffffffu, interesting);
            int c = __popc(m);
            // quad-sliced survivor processing: lane handles survivors slice,slice+4,...
            for (int j = slice; j < c; j += 4) {
                int bit = __fns(m, 0, j + 1);      // position of (j+1)-th set bit
                int fi = base + bit;
                float4 a  = c0[fi];
                float4 b  = c1[fi];
                float  cc = c2s[fi];
                float w0 = fmaf(a.x, px, fmaf(a.y, py, a.z));
                float w1 = fmaf(a.w, px, fmaf(b.x, py, b.y));
                float w2 = fmaf(b.z, px, fmaf(b.w, py, cc));
                float d  = fminf(w0, fminf(w1, w2));
                if (d > D_HI) {
                    covered = true;     // sigmoid == 1.0f in fp32 -> cov = 1
                } else if (d > D_LO) {
                    float tt = d * INV_SIGMA;
                    float prob = 1.0f / (1.0f + expf(-tt));
                    acc += log1pf(1e-12f - prob);
                }
            }
            // early exit: all 8 pixels of this warp covered?
            // (unconditional shuffles — every lane participates)
            bool oc1 = __shfl_xor_sync(0xffffffffu, covered, 1);
            bool c01 = covered || oc1;
            bool oc2 = __shfl_xor_sync(0xffffffffu, c01, 2);
            bool pcov = c01 || oc2;
            if (__all_sync(0xffffffffu, pcov)) break;
        }

        // ---- quad combine (unconditional shuffles; fp add commutative ->
        //      all four lanes get bit-identical sums; deterministic) ----
        bool  oc1 = __shfl_xor_sync(0xffffffffu, covered, 1);
        float oa1 = __shfl_xor_sync(0xffffffffu, acc, 1);
        covered = covered || oc1;
        acc += oa1;
        bool  oc2 = __shfl_xor_sync(0xffffffffu, covered, 2);
        float oa2 = __shfl_xor_sync(0xffffffffu, acc, 2);
        covered = covered || oc2;
        acc += oa2;
        cov = covered ? 1.0f : (1.0f - expf(acc));
    }

    // ---- phase 3: block reduction of squared error ----
    float v = 0.0f;
    if (slice == 0) {
        float df = cov - image_ref[pix];
        v = df * df;
    }
    #pragma unroll
    for (int off = 16; off > 0; off >>= 1)
        v += __shfl_down_sync(0xffffffffu, v, off);
    if (lane == 0) wsum[wid] = v;
    __syncthreads();
    if (tid == 0) {
        float bs = 0.0f;
        #pragma unroll
        for (int w = 0; w < 32; ++w) bs += wsum[w];
        g_partial[blockIdx.x] = bs;
        __threadfence();
        unsigned tkt = atomicAdd(&g_ticket, 1u);
        s_last = (tkt == gridDim.x - 1) ? 1 : 0;
    }
    __syncthreads();

    // ---- last block performs the deterministic final reduction ----
    if (s_last) {
        __threadfence();
        float sv = (tid < NBLK) ? g_partial[tid] : 0.0f;
        #pragma unroll
        for (int off = 16; off > 0; off >>= 1)
            sv += __shfl_down_sync(0xffffffffu, sv, off);
        if (lane == 0) wsum[wid] = sv;
        __syncthreads();
        if (tid == 0) {
            float tot = 0.0f;
            #pragma unroll
            for (int w = 0; w < 32; ++w) tot += wsum[w];
            out[0] = tot;
            g_ticket = 0;               // reset for next graph replay
        }
    }
}

extern "C" void kernel_launch(void* const* d_in, const int* in_sizes, int n_in,
                              void* d_out, int out_size) {
    const float* verts     = (const float*)d_in[0];  // (1,N,3)
    const float* K         = (const float*)d_in[1];  // (1,3,3)
    const float* R         = (const float*)d_in[2];  // (1,3,3)
    const float* t         = (const float*)d_in[3];  // (1,3)
    const float* image_ref = (const float*)d_in[4];  // (256,256)
    const int*   faces     = (const int*)d_in[5];    // (1,F,3)
    float* out = (float*)d_out;

    int F = in_sizes[5] / 3;
    if (F > FMAX) F = FMAX;

    fused_kernel<<<NBLK, TPB>>>(verts, K, R, t, faces, image_ref, F, out);
}